// round 16
// baseline (speedup 1.0000x reference)
#include <cuda_runtime.h>
#include <math.h>

// Problem constants
#define U_    128
#define NG    512
#define T_    512
#define B_    256
#define F_    64
#define OUT_  6

// LSTM R split (proven): 44 k-values in SMEM, 84 in registers
#define KSM   44
#define KRG   84
#define NQ_SM (KSM / 4)
#define NQ_RG (KRG / 4)

typedef unsigned long long ull;
typedef unsigned int uint32;

#define FMA2(acc, a, b) \
    asm("fma.rn.f32x2 %0, %1, %2, %0;" : "+l"(acc) \
        : "l"(__double_as_longlong(a)), "l"(__double_as_longlong(b)))

__device__ __forceinline__ float lo32(ull v) { return __int_as_float((int)(v & 0xffffffffull)); }
__device__ __forceinline__ float hi32(ull v) { return __int_as_float((int)(v >> 32)); }
__device__ __forceinline__ float unpack_sum(ull v) { return lo32(v) + hi32(v); }

__device__ __forceinline__ float fast_sigmoid(float x) {
    return __fdividef(1.f, 1.f + __expf(-x));
}
__device__ __forceinline__ float fast_tanh(float x) {
    float e = __expf(fminf(-2.f * x, 80.f));
    return __fdividef(1.f - e, 1.f + e);
}

__device__ __forceinline__ float f2tf(float f) {
    uint32 r;
    asm("cvt.rna.tf32.f32 %0, %1;" : "=r"(r) : "f"(f));
    return __uint_as_float(r);
}

// ---------------- scratch ----------------
__device__ float g_xw[(size_t)B_ * T_ * NG];
__device__ float g_h [(size_t)B_ * T_ * U_];
__device__ float g_RT[3][NG * U_];

// ---------------- R transpose ----------------
__global__ void k_transpose_R(const float* __restrict__ R, int layer) {
    int j = blockIdx.x;
    int k = threadIdx.x;
    g_RT[layer][j * U_ + k] = R[k * NG + j];
}

// ---------------- GEMM: tf32 tensor-core mma (R14 exact) ----------------
#define GBM 128
#define GBN 128
#define BK2 16
#define SPAD 8
__global__ __launch_bounds__(256, 2) void k_gemm_xw(const float* __restrict__ Ain,
                                                    const float* __restrict__ W,
                                                    const float* __restrict__ bias,
                                                    int K) {
    const float* A = Ain ? Ain : g_h;
    __shared__ float As[2][BK2][GBM + SPAD];
    __shared__ float Bs[2][BK2][GBN + SPAD];
    const int brow = blockIdx.y * GBM;
    const int bcol = blockIdx.x * GBN;
    const int tid = threadIdx.x;
    const int wid = tid >> 5, lane = tid & 31;
    const int wm = wid >> 1, wn = wid & 1;
    const int grp = lane >> 2, tig = lane & 3;

    const int a_m = tid >> 1;
    const int a_k = (tid & 1) * 8;
    const int b_k = tid >> 5;
    const int b_n = (tid & 31) * 4;

    float c[2][8][4];
    #pragma unroll
    for (int mt = 0; mt < 2; mt++)
        #pragma unroll
        for (int nt = 0; nt < 8; nt++)
            #pragma unroll
            for (int i = 0; i < 4; i++) c[mt][nt][i] = 0.f;

    const float* a_ptr  = &A[(size_t)(brow + a_m) * K + a_k];
    const float* b_ptr0 = &W[(size_t)b_k * NG + bcol + b_n];
    const float* b_ptr1 = &W[(size_t)(b_k + 8) * NG + bcol + b_n];

    float4 ar0 = *reinterpret_cast<const float4*>(a_ptr);
    float4 ar1 = *reinterpret_cast<const float4*>(a_ptr + 4);
    float4 br0 = *reinterpret_cast<const float4*>(b_ptr0);
    float4 br1 = *reinterpret_cast<const float4*>(b_ptr1);
    As[0][a_k + 0][a_m] = f2tf(ar0.x); As[0][a_k + 1][a_m] = f2tf(ar0.y);
    As[0][a_k + 2][a_m] = f2tf(ar0.z); As[0][a_k + 3][a_m] = f2tf(ar0.w);
    As[0][a_k + 4][a_m] = f2tf(ar1.x); As[0][a_k + 5][a_m] = f2tf(ar1.y);
    As[0][a_k + 6][a_m] = f2tf(ar1.z); As[0][a_k + 7][a_m] = f2tf(ar1.w);
    {
        float4 t0 = make_float4(f2tf(br0.x), f2tf(br0.y), f2tf(br0.z), f2tf(br0.w));
        float4 t1 = make_float4(f2tf(br1.x), f2tf(br1.y), f2tf(br1.z), f2tf(br1.w));
        *reinterpret_cast<float4*>(&Bs[0][b_k][b_n])     = t0;
        *reinterpret_cast<float4*>(&Bs[0][b_k + 8][b_n]) = t1;
    }
    __syncthreads();

    const int nk = K / BK2;
    for (int kb = 0; kb < nk; kb++) {
        const int cur = kb & 1;
        const int nxt = cur ^ 1;
        if (kb + 1 < nk) {
            const int k0 = (kb + 1) * BK2;
            ar0 = *reinterpret_cast<const float4*>(a_ptr + k0);
            ar1 = *reinterpret_cast<const float4*>(a_ptr + k0 + 4);
            br0 = *reinterpret_cast<const float4*>(b_ptr0 + (size_t)k0 * NG);
            br1 = *reinterpret_cast<const float4*>(b_ptr1 + (size_t)k0 * NG);
        }

        #pragma unroll
        for (int ks = 0; ks < 2; ks++) {
            const int kk = ks * 8 + tig;
            uint32 afr[2][4];
            #pragma unroll
            for (int mt = 0; mt < 2; mt++) {
                const int r0 = wm * 32 + mt * 16 + grp;
                afr[mt][0] = __float_as_uint(As[cur][kk][r0]);
                afr[mt][1] = __float_as_uint(As[cur][kk][r0 + 8]);
                afr[mt][2] = __float_as_uint(As[cur][kk + 4][r0]);
                afr[mt][3] = __float_as_uint(As[cur][kk + 4][r0 + 8]);
            }
            uint32 bfr[8][2];
            #pragma unroll
            for (int nt = 0; nt < 8; nt++) {
                const int n0 = wn * 64 + nt * 8 + grp;
                bfr[nt][0] = __float_as_uint(Bs[cur][kk][n0]);
                bfr[nt][1] = __float_as_uint(Bs[cur][kk + 4][n0]);
            }
            #pragma unroll
            for (int mt = 0; mt < 2; mt++)
                #pragma unroll
                for (int nt = 0; nt < 8; nt++) {
                    asm volatile(
                        "mma.sync.aligned.m16n8k8.row.col.f32.tf32.tf32.f32 "
                        "{%0,%1,%2,%3}, {%4,%5,%6,%7}, {%8,%9}, {%0,%1,%2,%3};"
                        : "+f"(c[mt][nt][0]), "+f"(c[mt][nt][1]),
                          "+f"(c[mt][nt][2]), "+f"(c[mt][nt][3])
                        : "r"(afr[mt][0]), "r"(afr[mt][1]),
                          "r"(afr[mt][2]), "r"(afr[mt][3]),
                          "r"(bfr[nt][0]), "r"(bfr[nt][1]));
                }
        }

        if (kb + 1 < nk) {
            As[nxt][a_k + 0][a_m] = f2tf(ar0.x); As[nxt][a_k + 1][a_m] = f2tf(ar0.y);
            As[nxt][a_k + 2][a_m] = f2tf(ar0.z); As[nxt][a_k + 3][a_m] = f2tf(ar0.w);
            As[nxt][a_k + 4][a_m] = f2tf(ar1.x); As[nxt][a_k + 5][a_m] = f2tf(ar1.y);
            As[nxt][a_k + 6][a_m] = f2tf(ar1.z); As[nxt][a_k + 7][a_m] = f2tf(ar1.w);
            float4 t0 = make_float4(f2tf(br0.x), f2tf(br0.y), f2tf(br0.z), f2tf(br0.w));
            float4 t1 = make_float4(f2tf(br1.x), f2tf(br1.y), f2tf(br1.z), f2tf(br1.w));
            *reinterpret_cast<float4*>(&Bs[nxt][b_k][b_n])     = t0;
            *reinterpret_cast<float4*>(&Bs[nxt][b_k + 8][b_n]) = t1;
        }
        __syncthreads();
    }

    #pragma unroll
    for (int nt = 0; nt < 8; nt++) {
        const int col = bcol + wn * 64 + nt * 8 + tig * 2;
        const float bb0 = bias[col], bb1 = bias[col + 1];
        #pragma unroll
        for (int mt = 0; mt < 2; mt++) {
            const size_t row0 = (size_t)(brow + wm * 32 + mt * 16 + grp);
            float2 o0 = make_float2(c[mt][nt][0] + bb0, c[mt][nt][1] + bb1);
            float2 o1 = make_float2(c[mt][nt][2] + bb0, c[mt][nt][3] + bb1);
            *reinterpret_cast<float2*>(&g_xw[row0 * NG + col])       = o0;
            *reinterpret_cast<float2*>(&g_xw[(row0 + 8) * NG + col]) = o1;
        }
    }
}

// ---------------- LSTM scan: lane-pair gate fusion + PING-PONG h, one barrier ----------------
// Thread tid: k = tid>>1, odd = tid&1. c0 = k + odd*128 (i/f), c1 = c0+256 (g/o).
// Even lane shfls i*g to odd lane; odd lane owns cell state, writes h to the
// ALTERNATE h buffer (ping-pong) so the single barrier is race-free.
#define LSTM_SMEM_FLOATS 30000
#define LSTM_SMEM_BYTES  (LSTM_SMEM_FLOATS * 4)

__global__ __launch_bounds__(256) void k_lstm(int layer) {
    extern __shared__ float smem[];
    float* sR = smem;                          // [512][KSM]
    float* sh = sR + NG * KSM;                 // ping-pong: [2][2*U_]

    const int tid = threadIdx.x;
    const int k   = tid >> 1;
    const int odd = tid & 1;
    const int c0  = k + odd * 128;             // i (even) or f (odd)
    const int c1  = c0 + 256;                  // g (even) or o (odd)
    const int b0  = blockIdx.x * 2;
    const float* RT = g_RT[layer];

    for (int i = tid; i < NG * KSM; i += 256) {
        int col = i / KSM, kk = i - col * KSM;
        sR[i] = RT[col * U_ + kk];
    }
    double rr0[NQ_RG * 2], rr1[NQ_RG * 2];
    {
        const double2* rg0 = reinterpret_cast<const double2*>(RT + c0 * U_ + KSM);
        const double2* rg1 = reinterpret_cast<const double2*>(RT + c1 * U_ + KSM);
        #pragma unroll
        for (int q = 0; q < NQ_RG; q++) {
            double2 v0 = rg0[q];
            double2 v1 = rg1[q];
            rr0[2 * q] = v0.x; rr0[2 * q + 1] = v0.y;
            rr1[2 * q] = v1.x; rr1[2 * q + 1] = v1.y;
        }
    }
    sh[tid] = 0.f;                             // zero buffer 0 ([2*U_] floats)
    __syncthreads();

    const double2* rs0 = reinterpret_cast<const double2*>(sR + c0 * KSM);
    const double2* rs1 = reinterpret_cast<const double2*>(sR + c1 * KSM);
    const size_t xw0base = (size_t)b0 * T_ * NG;
    const size_t xw1base = (size_t)(b0 + 1) * T_ * NG;

    float cr0 = 0.f, cr1 = 0.f;                // cell state (odd lanes own it)
    const float act_sc  = odd ? 1.f : 2.f;     // sigmoid vs tanh exponent scale
    const float act_one = odd ? 1.f : 0.f;     // numerator select

    float pf00 = __ldcs(&g_xw[xw0base + c0]);
    float pf01 = __ldcs(&g_xw[xw0base + c1]);
    float pf10 = __ldcs(&g_xw[xw1base + c0]);
    float pf11 = __ldcs(&g_xw[xw1base + c1]);

    for (int t = 0; t < T_; t++) {
        const float* shr = sh + (t & 1) * 2 * U_;         // read buffer
        float*       shw = sh + ((t + 1) & 1) * 2 * U_;   // write buffer
        const double2* h0p = reinterpret_cast<const double2*>(shr);
        const double2* h1p = reinterpret_cast<const double2*>(shr + U_);

        ull a00 = (ull)__float_as_uint(pf00);
        ull a01 = (ull)__float_as_uint(pf01);
        ull a10 = (ull)__float_as_uint(pf10);
        ull a11 = (ull)__float_as_uint(pf11);
        if (t + 1 < T_) {
            size_t o0 = xw0base + (size_t)(t + 1) * NG;
            size_t o1 = xw1base + (size_t)(t + 1) * NG;
            pf00 = __ldcs(&g_xw[o0 + c0]);
            pf01 = __ldcs(&g_xw[o0 + c1]);
            pf10 = __ldcs(&g_xw[o1 + c0]);
            pf11 = __ldcs(&g_xw[o1 + c1]);
        }

        #pragma unroll
        for (int q = 0; q < NQ_SM; q++) {
            double2 r0 = rs0[q];
            double2 r1 = rs1[q];
            double2 h0 = h0p[q];
            double2 h1 = h1p[q];
            FMA2(a00, r0.x, h0.x); FMA2(a01, r1.x, h0.x);
            FMA2(a10, r0.x, h1.x); FMA2(a11, r1.x, h1.x);
            FMA2(a00, r0.y, h0.y); FMA2(a01, r1.y, h0.y);
            FMA2(a10, r0.y, h1.y); FMA2(a11, r1.y, h1.y);
        }
        #pragma unroll
        for (int q = 0; q < NQ_RG; q++) {
            double2 h0 = h0p[NQ_SM + q];
            double2 h1 = h1p[NQ_SM + q];
            FMA2(a00, rr0[2 * q], h0.x); FMA2(a01, rr1[2 * q], h0.x);
            FMA2(a10, rr0[2 * q], h1.x); FMA2(a11, rr1[2 * q], h1.x);
            FMA2(a00, rr0[2 * q + 1], h0.y); FMA2(a01, rr1[2 * q + 1], h0.y);
            FMA2(a10, rr0[2 * q + 1], h1.y); FMA2(a11, rr1[2 * q + 1], h1.y);
        }

        float z00 = unpack_sum(a00);   // c0 gate: i (even) / f (odd)
        float z01 = unpack_sum(a01);   // c1 gate: g (even) / o (odd)
        float z10 = unpack_sum(a10);
        float z11 = unpack_sum(a11);

        float s00 = fast_sigmoid(z00);
        float s10 = fast_sigmoid(z10);
        float e01 = __expf(fminf(-act_sc * z01, 80.f));
        float e11 = __expf(fminf(-act_sc * z11, 80.f));
        float s01 = __fdividef(act_one + (1.f - act_one) * (1.f - e01), 1.f + e01);
        float s11 = __fdividef(act_one + (1.f - act_one) * (1.f - e11), 1.f + e11);

        float p0 = s00 * s01;                   // even: i*g (odd lanes compute garbage)
        float p1 = s10 * s11;
        float pp0 = __shfl_xor_sync(0xffffffffu, p0, 1);
        float pp1 = __shfl_xor_sync(0xffffffffu, p1, 1);

        if (odd) {                              // f = s00/s10, o = s01/s11
            cr0 = fmaf(s00, cr0, pp0);
            cr1 = fmaf(s10, cr1, pp1);
            float h0 = s01 * fast_tanh(cr0);
            float h1 = s11 * fast_tanh(cr1);
            shw[k]      = h0;
            shw[U_ + k] = h1;
            g_h[((size_t)b0 * T_ + t) * U_ + k]       = h0;
            g_h[((size_t)(b0 + 1) * T_ + t) * U_ + k] = h1;
        }
        __syncthreads();                        // single barrier (ping-pong = race-free)
    }
}

// ---------------- dense head ----------------
__global__ void k_dense(const float* __restrict__ Wd, const float* __restrict__ bd,
                        float* __restrict__ out) {
    int idx = blockIdx.x * 256 + threadIdx.x;
    if (idx >= B_ * OUT_) return;
    int b = idx / OUT_, j = idx % OUT_;
    const float* hrow = &g_h[((size_t)b * T_ + (T_ - 1)) * U_];
    float s = bd[j];
    #pragma unroll
    for (int k = 0; k < U_; k++) s = fmaf(hrow[k], Wd[k * OUT_ + j], s);
    out[idx] = s;
}

// ---------------- launch ----------------
extern "C" void kernel_launch(void* const* d_in, const int* in_sizes, int n_in,
                              void* d_out, int out_size) {
    const float* x  = (const float*)d_in[0];
    const float* W0 = (const float*)d_in[1];
    const float* R0 = (const float*)d_in[2];
    const float* b0 = (const float*)d_in[3];
    const float* W1 = (const float*)d_in[4];
    const float* R1 = (const float*)d_in[5];
    const float* b1 = (const float*)d_in[6];
    const float* W2 = (const float*)d_in[7];
    const float* R2 = (const float*)d_in[8];
    const float* b2 = (const float*)d_in[9];
    const float* Wd = (const float*)d_in[10];
    const float* bd = (const float*)d_in[11];
    float* out = (float*)d_out;

    cudaFuncSetAttribute(k_lstm, cudaFuncAttributeMaxDynamicSharedMemorySize, LSTM_SMEM_BYTES);

    dim3 gemm_grid(NG / GBN, (B_ * T_) / GBM);

    // order: 0 t0, 1 gemm0(K=64), 2 lstm0, 3 gemm1(K=128) <- ncu capture slot
    k_transpose_R<<<NG, U_>>>(R0, 0);
    k_gemm_xw<<<gemm_grid, 256>>>(x, W0, b0, F_);
    k_lstm<<<B_ / 2, 256, LSTM_SMEM_BYTES>>>(0);
    k_gemm_xw<<<gemm_grid, 256>>>(nullptr, W1, b1, U_);
    k_transpose_R<<<NG, U_>>>(R1, 1);
    k_lstm<<<B_ / 2, 256, LSTM_SMEM_BYTES>>>(1);
    k_gemm_xw<<<gemm_grid, 256>>>(nullptr, W2, b2, U_);
    k_transpose_R<<<NG, U_>>>(R2, 2);
    k_lstm<<<B_ / 2, 256, LSTM_SMEM_BYTES>>>(2);

    k_dense<<<(B_ * OUT_ + 255) / 256, 256>>>(Wd, bd, out);
}

// round 17
// speedup vs baseline: 1.1494x; 1.1494x over previous
#include <cuda_runtime.h>
#include <math.h>

// Problem constants
#define U_    128
#define NG    512
#define T_    512
#define B_    256
#define F_    64
#define OUT_  6

// LSTM R split (proven): 44 k-values in SMEM, 84 in registers
#define KSM   44
#define KRG   84
#define NQ_SM (KSM / 4)
#define NQ_RG (KRG / 4)

typedef unsigned long long ull;
typedef unsigned int uint32;

#define FMA2(acc, a, b) \
    asm("fma.rn.f32x2 %0, %1, %2, %0;" : "+l"(acc) \
        : "l"(__double_as_longlong(a)), "l"(__double_as_longlong(b)))

__device__ __forceinline__ float lo32(ull v) { return __int_as_float((int)(v & 0xffffffffull)); }
__device__ __forceinline__ float hi32(ull v) { return __int_as_float((int)(v >> 32)); }
__device__ __forceinline__ float unpack_sum(ull v) { return lo32(v) + hi32(v); }

__device__ __forceinline__ float fast_sigmoid(float x) {
    return __fdividef(1.f, 1.f + __expf(-x));
}
__device__ __forceinline__ float fast_tanh(float x) {
    float e = __expf(fminf(-2.f * x, 80.f));
    return __fdividef(1.f - e, 1.f + e);
}

__device__ __forceinline__ float f2tf(float f) {
    uint32 r;
    asm("cvt.rna.tf32.f32 %0, %1;" : "=r"(r) : "f"(f));
    return __uint_as_float(r);
}

// ---------------- scratch ----------------
__device__ float g_xw[(size_t)B_ * T_ * NG];
__device__ float g_h [(size_t)B_ * T_ * U_];
__device__ float g_RT[3][NG * U_];

// ---------------- R transpose ----------------
__global__ void k_transpose_R(const float* __restrict__ R, int layer) {
    int j = blockIdx.x;
    int k = threadIdx.x;
    g_RT[layer][j * U_ + k] = R[k * NG + j];
}

// ---------------- GEMM: tf32 tensor-core mma (R14 exact) ----------------
#define GBM 128
#define GBN 128
#define BK2 16
#define SPAD 8
__global__ __launch_bounds__(256, 2) void k_gemm_xw(const float* __restrict__ Ain,
                                                    const float* __restrict__ W,
                                                    const float* __restrict__ bias,
                                                    int K) {
    const float* A = Ain ? Ain : g_h;
    __shared__ float As[2][BK2][GBM + SPAD];
    __shared__ float Bs[2][BK2][GBN + SPAD];
    const int brow = blockIdx.y * GBM;
    const int bcol = blockIdx.x * GBN;
    const int tid = threadIdx.x;
    const int wid = tid >> 5, lane = tid & 31;
    const int wm = wid >> 1, wn = wid & 1;
    const int grp = lane >> 2, tig = lane & 3;

    const int a_m = tid >> 1;
    const int a_k = (tid & 1) * 8;
    const int b_k = tid >> 5;
    const int b_n = (tid & 31) * 4;

    float c[2][8][4];
    #pragma unroll
    for (int mt = 0; mt < 2; mt++)
        #pragma unroll
        for (int nt = 0; nt < 8; nt++)
            #pragma unroll
            for (int i = 0; i < 4; i++) c[mt][nt][i] = 0.f;

    const float* a_ptr  = &A[(size_t)(brow + a_m) * K + a_k];
    const float* b_ptr0 = &W[(size_t)b_k * NG + bcol + b_n];
    const float* b_ptr1 = &W[(size_t)(b_k + 8) * NG + bcol + b_n];

    float4 ar0 = *reinterpret_cast<const float4*>(a_ptr);
    float4 ar1 = *reinterpret_cast<const float4*>(a_ptr + 4);
    float4 br0 = *reinterpret_cast<const float4*>(b_ptr0);
    float4 br1 = *reinterpret_cast<const float4*>(b_ptr1);
    As[0][a_k + 0][a_m] = f2tf(ar0.x); As[0][a_k + 1][a_m] = f2tf(ar0.y);
    As[0][a_k + 2][a_m] = f2tf(ar0.z); As[0][a_k + 3][a_m] = f2tf(ar0.w);
    As[0][a_k + 4][a_m] = f2tf(ar1.x); As[0][a_k + 5][a_m] = f2tf(ar1.y);
    As[0][a_k + 6][a_m] = f2tf(ar1.z); As[0][a_k + 7][a_m] = f2tf(ar1.w);
    {
        float4 t0 = make_float4(f2tf(br0.x), f2tf(br0.y), f2tf(br0.z), f2tf(br0.w));
        float4 t1 = make_float4(f2tf(br1.x), f2tf(br1.y), f2tf(br1.z), f2tf(br1.w));
        *reinterpret_cast<float4*>(&Bs[0][b_k][b_n])     = t0;
        *reinterpret_cast<float4*>(&Bs[0][b_k + 8][b_n]) = t1;
    }
    __syncthreads();

    const int nk = K / BK2;
    for (int kb = 0; kb < nk; kb++) {
        const int cur = kb & 1;
        const int nxt = cur ^ 1;
        if (kb + 1 < nk) {
            const int k0 = (kb + 1) * BK2;
            ar0 = *reinterpret_cast<const float4*>(a_ptr + k0);
            ar1 = *reinterpret_cast<const float4*>(a_ptr + k0 + 4);
            br0 = *reinterpret_cast<const float4*>(b_ptr0 + (size_t)k0 * NG);
            br1 = *reinterpret_cast<const float4*>(b_ptr1 + (size_t)k0 * NG);
        }

        #pragma unroll
        for (int ks = 0; ks < 2; ks++) {
            const int kk = ks * 8 + tig;
            uint32 afr[2][4];
            #pragma unroll
            for (int mt = 0; mt < 2; mt++) {
                const int r0 = wm * 32 + mt * 16 + grp;
                afr[mt][0] = __float_as_uint(As[cur][kk][r0]);
                afr[mt][1] = __float_as_uint(As[cur][kk][r0 + 8]);
                afr[mt][2] = __float_as_uint(As[cur][kk + 4][r0]);
                afr[mt][3] = __float_as_uint(As[cur][kk + 4][r0 + 8]);
            }
            uint32 bfr[8][2];
            #pragma unroll
            for (int nt = 0; nt < 8; nt++) {
                const int n0 = wn * 64 + nt * 8 + grp;
                bfr[nt][0] = __float_as_uint(Bs[cur][kk][n0]);
                bfr[nt][1] = __float_as_uint(Bs[cur][kk + 4][n0]);
            }
            #pragma unroll
            for (int mt = 0; mt < 2; mt++)
                #pragma unroll
                for (int nt = 0; nt < 8; nt++) {
                    asm volatile(
                        "mma.sync.aligned.m16n8k8.row.col.f32.tf32.tf32.f32 "
                        "{%0,%1,%2,%3}, {%4,%5,%6,%7}, {%8,%9}, {%0,%1,%2,%3};"
                        : "+f"(c[mt][nt][0]), "+f"(c[mt][nt][1]),
                          "+f"(c[mt][nt][2]), "+f"(c[mt][nt][3])
                        : "r"(afr[mt][0]), "r"(afr[mt][1]),
                          "r"(afr[mt][2]), "r"(afr[mt][3]),
                          "r"(bfr[nt][0]), "r"(bfr[nt][1]));
                }
        }

        if (kb + 1 < nk) {
            As[nxt][a_k + 0][a_m] = f2tf(ar0.x); As[nxt][a_k + 1][a_m] = f2tf(ar0.y);
            As[nxt][a_k + 2][a_m] = f2tf(ar0.z); As[nxt][a_k + 3][a_m] = f2tf(ar0.w);
            As[nxt][a_k + 4][a_m] = f2tf(ar1.x); As[nxt][a_k + 5][a_m] = f2tf(ar1.y);
            As[nxt][a_k + 6][a_m] = f2tf(ar1.z); As[nxt][a_k + 7][a_m] = f2tf(ar1.w);
            float4 t0 = make_float4(f2tf(br0.x), f2tf(br0.y), f2tf(br0.z), f2tf(br0.w));
            float4 t1 = make_float4(f2tf(br1.x), f2tf(br1.y), f2tf(br1.z), f2tf(br1.w));
            *reinterpret_cast<float4*>(&Bs[nxt][b_k][b_n])     = t0;
            *reinterpret_cast<float4*>(&Bs[nxt][b_k + 8][b_n]) = t1;
        }
        __syncthreads();
    }

    #pragma unroll
    for (int nt = 0; nt < 8; nt++) {
        const int col = bcol + wn * 64 + nt * 8 + tig * 2;
        const float bb0 = bias[col], bb1 = bias[col + 1];
        #pragma unroll
        for (int mt = 0; mt < 2; mt++) {
            const size_t row0 = (size_t)(brow + wm * 32 + mt * 16 + grp);
            float2 o0 = make_float2(c[mt][nt][0] + bb0, c[mt][nt][1] + bb1);
            float2 o1 = make_float2(c[mt][nt][2] + bb0, c[mt][nt][3] + bb1);
            *reinterpret_cast<float2*>(&g_xw[row0 * NG + col])       = o0;
            *reinterpret_cast<float2*>(&g_xw[(row0 + 8) * NG + col]) = o1;
        }
    }
}

// ---------------- LSTM: lane-pair fusion + ping-pong h + THREAD-ORDERED sR ----------------
// Thread tid: k = tid>>1, odd = tid&1. c0 = k + odd*128 (i/f), c1 = c0+256 (g/o).
// sR is staged in THREAD-INDEX order: slot tid holds column c0(tid), slot tid+256
// holds c1(tid). So rs0 = sR + tid*KSM -> identical conflict-free lane pattern to R14.
#define LSTM_SMEM_FLOATS 30000
#define LSTM_SMEM_BYTES  (LSTM_SMEM_FLOATS * 4)

__global__ __launch_bounds__(256) void k_lstm(int layer) {
    extern __shared__ float smem[];
    float* sR = smem;                          // [512][KSM], thread-ordered slots
    float* sh = sR + NG * KSM;                 // ping-pong: [2][2*U_]

    const int tid = threadIdx.x;
    const int k   = tid >> 1;
    const int odd = tid & 1;
    const int c0  = k + odd * 128;             // i (even) or f (odd)
    const int c1  = c0 + 256;                  // g (even) or o (odd)
    const int b0  = blockIdx.x * 2;
    const float* RT = g_RT[layer];

    // stage R permuted: slot s (<256) <- column (s>>1)+(s&1)*128; slot s+256 <- +256
    for (int i = tid; i < NG * KSM; i += 256) {
        int slot = i / KSM, kk = i - slot * KSM;
        int base = slot & 255;
        int col = (base >> 1) + (base & 1) * 128 + (slot >> 8) * 256;
        sR[i] = RT[col * U_ + kk];
    }
    double rr0[NQ_RG * 2], rr1[NQ_RG * 2];
    {
        const double2* rg0 = reinterpret_cast<const double2*>(RT + c0 * U_ + KSM);
        const double2* rg1 = reinterpret_cast<const double2*>(RT + c1 * U_ + KSM);
        #pragma unroll
        for (int q = 0; q < NQ_RG; q++) {
            double2 v0 = rg0[q];
            double2 v1 = rg1[q];
            rr0[2 * q] = v0.x; rr0[2 * q + 1] = v0.y;
            rr1[2 * q] = v1.x; rr1[2 * q + 1] = v1.y;
        }
    }
    sh[tid] = 0.f;                             // zero buffer 0
    __syncthreads();

    // conflict-free lane pattern (uniform 44-float stride, as R14)
    const double2* rs0 = reinterpret_cast<const double2*>(sR + tid * KSM);
    const double2* rs1 = reinterpret_cast<const double2*>(sR + (tid + 256) * KSM);
    const size_t xw0base = (size_t)b0 * T_ * NG;
    const size_t xw1base = (size_t)(b0 + 1) * T_ * NG;

    float cr0 = 0.f, cr1 = 0.f;                // cell state (odd lanes own it)
    const float act_sc  = odd ? 1.f : 2.f;
    const float act_one = odd ? 1.f : 0.f;

    float pf00 = __ldcs(&g_xw[xw0base + c0]);
    float pf01 = __ldcs(&g_xw[xw0base + c1]);
    float pf10 = __ldcs(&g_xw[xw1base + c0]);
    float pf11 = __ldcs(&g_xw[xw1base + c1]);

    for (int t = 0; t < T_; t++) {
        const float* shr = sh + (t & 1) * 2 * U_;
        float*       shw = sh + ((t + 1) & 1) * 2 * U_;
        const double2* h0p = reinterpret_cast<const double2*>(shr);
        const double2* h1p = reinterpret_cast<const double2*>(shr + U_);

        ull a00 = (ull)__float_as_uint(pf00);
        ull a01 = (ull)__float_as_uint(pf01);
        ull a10 = (ull)__float_as_uint(pf10);
        ull a11 = (ull)__float_as_uint(pf11);
        if (t + 1 < T_) {
            size_t o0 = xw0base + (size_t)(t + 1) * NG;
            size_t o1 = xw1base + (size_t)(t + 1) * NG;
            pf00 = __ldcs(&g_xw[o0 + c0]);
            pf01 = __ldcs(&g_xw[o0 + c1]);
            pf10 = __ldcs(&g_xw[o1 + c0]);
            pf11 = __ldcs(&g_xw[o1 + c1]);
        }

        #pragma unroll
        for (int q = 0; q < NQ_SM; q++) {
            double2 r0 = rs0[q];
            double2 r1 = rs1[q];
            double2 h0 = h0p[q];
            double2 h1 = h1p[q];
            FMA2(a00, r0.x, h0.x); FMA2(a01, r1.x, h0.x);
            FMA2(a10, r0.x, h1.x); FMA2(a11, r1.x, h1.x);
            FMA2(a00, r0.y, h0.y); FMA2(a01, r1.y, h0.y);
            FMA2(a10, r0.y, h1.y); FMA2(a11, r1.y, h1.y);
        }
        #pragma unroll
        for (int q = 0; q < NQ_RG; q++) {
            double2 h0 = h0p[NQ_SM + q];
            double2 h1 = h1p[NQ_SM + q];
            FMA2(a00, rr0[2 * q], h0.x); FMA2(a01, rr1[2 * q], h0.x);
            FMA2(a10, rr0[2 * q], h1.x); FMA2(a11, rr1[2 * q], h1.x);
            FMA2(a00, rr0[2 * q + 1], h0.y); FMA2(a01, rr1[2 * q + 1], h0.y);
            FMA2(a10, rr0[2 * q + 1], h1.y); FMA2(a11, rr1[2 * q + 1], h1.y);
        }

        float z00 = unpack_sum(a00);   // i (even) / f (odd)
        float z01 = unpack_sum(a01);   // g (even) / o (odd)
        float z10 = unpack_sum(a10);
        float z11 = unpack_sum(a11);

        float s00 = fast_sigmoid(z00);
        float s10 = fast_sigmoid(z10);
        float e01 = __expf(fminf(-act_sc * z01, 80.f));
        float e11 = __expf(fminf(-act_sc * z11, 80.f));
        float s01 = __fdividef(act_one + (1.f - act_one) * (1.f - e01), 1.f + e01);
        float s11 = __fdividef(act_one + (1.f - act_one) * (1.f - e11), 1.f + e11);

        float p0 = s00 * s01;                   // even lanes: i*g
        float p1 = s10 * s11;
        float pp0 = __shfl_xor_sync(0xffffffffu, p0, 1);
        float pp1 = __shfl_xor_sync(0xffffffffu, p1, 1);

        if (odd) {                              // f = s00/s10, o = s01/s11
            cr0 = fmaf(s00, cr0, pp0);
            cr1 = fmaf(s10, cr1, pp1);
            float h0 = s01 * fast_tanh(cr0);
            float h1 = s11 * fast_tanh(cr1);
            shw[k]      = h0;
            shw[U_ + k] = h1;
            g_h[((size_t)b0 * T_ + t) * U_ + k]       = h0;
            g_h[((size_t)(b0 + 1) * T_ + t) * U_ + k] = h1;
        }
        __syncthreads();                        // single barrier (ping-pong = race-free)
    }
}

// ---------------- dense head ----------------
__global__ void k_dense(const float* __restrict__ Wd, const float* __restrict__ bd,
                        float* __restrict__ out) {
    int idx = blockIdx.x * 256 + threadIdx.x;
    if (idx >= B_ * OUT_) return;
    int b = idx / OUT_, j = idx % OUT_;
    const float* hrow = &g_h[((size_t)b * T_ + (T_ - 1)) * U_];
    float s = bd[j];
    #pragma unroll
    for (int k = 0; k < U_; k++) s = fmaf(hrow[k], Wd[k * OUT_ + j], s);
    out[idx] = s;
}

// ---------------- launch ----------------
extern "C" void kernel_launch(void* const* d_in, const int* in_sizes, int n_in,
                              void* d_out, int out_size) {
    const float* x  = (const float*)d_in[0];
    const float* W0 = (const float*)d_in[1];
    const float* R0 = (const float*)d_in[2];
    const float* b0 = (const float*)d_in[3];
    const float* W1 = (const float*)d_in[4];
    const float* R1 = (const float*)d_in[5];
    const float* b1 = (const float*)d_in[6];
    const float* W2 = (const float*)d_in[7];
    const float* R2 = (const float*)d_in[8];
    const float* b2 = (const float*)d_in[9];
    const float* Wd = (const float*)d_in[10];
    const float* bd = (const float*)d_in[11];
    float* out = (float*)d_out;

    cudaFuncSetAttribute(k_lstm, cudaFuncAttributeMaxDynamicSharedMemorySize, LSTM_SMEM_BYTES);

    dim3 gemm_grid(NG / GBN, (B_ * T_) / GBM);

    // order: 0 t0, 1 gemm0(K=64), 2 lstm0, 3 gemm1(K=128) <- ncu capture slot
    k_transpose_R<<<NG, U_>>>(R0, 0);
    k_gemm_xw<<<gemm_grid, 256>>>(x, W0, b0, F_);
    k_lstm<<<B_ / 2, 256, LSTM_SMEM_BYTES>>>(0);
    k_gemm_xw<<<gemm_grid, 256>>>(nullptr, W1, b1, U_);
    k_transpose_R<<<NG, U_>>>(R1, 1);
    k_lstm<<<B_ / 2, 256, LSTM_SMEM_BYTES>>>(1);
    k_gemm_xw<<<gemm_grid, 256>>>(nullptr, W2, b2, U_);
    k_transpose_R<<<NG, U_>>>(R2, 2);
    k_lstm<<<B_ / 2, 256, LSTM_SMEM_BYTES>>>(2);

    k_dense<<<(B_ * OUT_ + 255) / 256, 256>>>(Wd, bd, out);
}